// round 6
// baseline (speedup 1.0000x reference)
#include <cuda_runtime.h>

// ============================================================================
// MultiHeadAttentionQuantum — algebraic form.
// Per (token, head): circuit = fixed 16x16 unitary U_h applied to the real
// rank-1 vector v = ⊗_q (cos(x_q/2), sin(x_q/2)).
//   ev_i = v^T B_i v,  B_i = Σ_j s_ij Re(U_j^† U_j)   (real symmetric)
// Since cos² = (1+C)/2, sin² = (1−C)/2, cos·sin = S/2  (C=cos x, S=sin x),
// ev_i is multilinear in {1, C_q, S_q}:  ev_i = Σ_{m∈3^4} T_i[m] Φ_m(x),
// 81 basis terms. T precomputed per head; ev kernel does a factored
// (9 x 9) dot per (token, head) — 2.4x fewer FMAs than the direct matvec.
// ============================================================================

#define NQ      4
#define DIM     16
#define NH      8
#define NLAYERS 2
#define EMB     32
#define NTOK    (32 * 4096)
#define NBASIS  81

typedef unsigned long long ull;

// ---- packed f32x2 helpers (Blackwell sm_103a) ------------------------------
__device__ __forceinline__ ull pk(float lo, float hi) {
    ull r; asm("mov.b64 %0, {%1, %2};" : "=l"(r) : "f"(lo), "f"(hi)); return r;
}
__device__ __forceinline__ void upk(ull v, float& lo, float& hi) {
    asm("mov.b64 {%0, %1}, %2;" : "=f"(lo), "=f"(hi) : "l"(v));
}
__device__ __forceinline__ ull f2mul(ull a, ull b) {
    ull d; asm("mul.rn.f32x2 %0, %1, %2;" : "=l"(d) : "l"(a), "l"(b)); return d;
}
__device__ __forceinline__ ull f2fma(ull a, ull b, ull c) {
    ull d; asm("fma.rn.f32x2 %0, %1, %2, %3;" : "=l"(d) : "l"(a), "l"(b), "l"(c)); return d;
}

// ---- global scratch (static device arrays; no allocation) ------------------
__device__ ull   g_T[NH * 4 * NBASIS];            // dup'd f32x2 T tensor
__device__ float g_ev[(size_t)NTOK * EMB];        // 16 MB scratch

// ============================================================================
// Gate helpers with COMPILE-TIME masks (static register indexing — no local
// memory demotion, which was costing 28 us in the old precompute kernel).
// ============================================================================
template<int M>
__device__ __forceinline__ void rot3(float* cr, float* ci, const float* p) {
    float c, s;
    // ---- RX(t)
    __sincosf(0.5f * p[0], &s, &c);
#pragma unroll
    for (int j = 0; j < DIM; ++j) if (!(j & M)) {
        const int j1 = j | M;
        float a0r = cr[j],  a0i = ci[j];
        float a1r = cr[j1], a1i = ci[j1];
        cr[j]  = c * a0r + s * a1i;   ci[j]  = c * a0i - s * a1r;
        cr[j1] = c * a1r + s * a0i;   ci[j1] = c * a1i - s * a0r;
    }
    // ---- RY(t)
    __sincosf(0.5f * p[1], &s, &c);
#pragma unroll
    for (int j = 0; j < DIM; ++j) if (!(j & M)) {
        const int j1 = j | M;
        float a0r = cr[j],  a0i = ci[j];
        float a1r = cr[j1], a1i = ci[j1];
        cr[j]  = c * a0r - s * a1r;   ci[j]  = c * a0i - s * a1i;
        cr[j1] = s * a0r + c * a1r;   ci[j1] = s * a0i + c * a1i;
    }
    // ---- RZ(t)
    __sincosf(0.5f * p[2], &s, &c);
#pragma unroll
    for (int j = 0; j < DIM; ++j) if (!(j & M)) {
        const int j1 = j | M;
        float a0r = cr[j],  a0i = ci[j];
        float a1r = cr[j1], a1i = ci[j1];
        cr[j]  = c * a0r + s * a0i;   ci[j]  = c * a0i - s * a0r;
        cr[j1] = c * a1r - s * a1i;   ci[j1] = c * a1i + s * a1r;
    }
}

template<int CM, int TM>
__device__ __forceinline__ void cnot_g(float* cr, float* ci) {
#pragma unroll
    for (int j = 0; j < DIM; ++j) if ((j & CM) && !(j & TM)) {
        const int j1 = j | TM;
        float tr = cr[j]; cr[j] = cr[j1]; cr[j1] = tr;
        float ti = ci[j]; ci[j] = ci[j1]; ci[j1] = ti;
    }
}

// ============================================================================
// Kernel 1: per head, build U, then B_i, then the 4x81 T tensor.
// One block per head (8 blocks x 128 threads).
// ============================================================================
__global__ void precompute_T_kernel(const float* __restrict__ params) {
    __shared__ float sUr[DIM * DIM], sUi[DIM * DIM];
    __shared__ float sB[4 * 256];
    const int h = blockIdx.x;
    const int tid = threadIdx.x;

    // ---- stage 1: threads 0..15 each evolve one COLUMN of U ----
    if (tid < DIM) {
        float cr[DIM], ci[DIM];
#pragma unroll
        for (int j = 0; j < DIM; ++j) { cr[j] = (j == tid) ? 1.0f : 0.0f; ci[j] = 0.0f; }
#pragma unroll
        for (int l = 0; l < NLAYERS; ++l) {
            const float* pb = params + (h * NLAYERS + l) * NQ * 3;
            rot3<8>(cr, ci, pb + 0);   // qubit 0 (bit 3)
            rot3<4>(cr, ci, pb + 3);   // qubit 1 (bit 2)
            rot3<2>(cr, ci, pb + 6);   // qubit 2 (bit 1)
            rot3<1>(cr, ci, pb + 9);   // qubit 3 (bit 0)
            cnot_g<8, 4>(cr, ci);      // (0,1)
            cnot_g<4, 2>(cr, ci);      // (1,2)
            cnot_g<2, 1>(cr, ci);      // (2,3)
            cnot_g<1, 8>(cr, ci);      // (3,0)
        }
#pragma unroll
        for (int j = 0; j < DIM; ++j) { sUr[j * DIM + tid] = cr[j]; sUi[j * DIM + tid] = ci[j]; }
    }
    __syncthreads();

    // ---- stage 2: B_i[k][k'] = Σ_j s_ij (Ur_jk Ur_jk' + Ui_jk Ui_jk') ----
    for (int idx = tid; idx < 4 * 256; idx += 128) {
        const int i  = idx >> 8;
        const int k  = (idx >> 4) & 15;
        const int kp = idx & 15;
        float sum = 0.0f;
#pragma unroll
        for (int j = 0; j < DIM; ++j) {
            float t = sUr[j * DIM + k] * sUr[j * DIM + kp]
                    + sUi[j * DIM + k] * sUi[j * DIM + kp];
            sum += ((j >> (3 - i)) & 1) ? -t : t;
        }
        sB[idx] = sum;
    }
    __syncthreads();

    // ---- stage 3: monomial transform to T_i[m], m = (m0 m1 m2 m3) base 3 ----
    // per-qubit coef on (1, C, S): (kq==kq'): m=0 -> +1 ; m=1 -> (kq? -1:+1) ; m=2 -> 0
    //                              (kq!=kq'): m=2 -> +1 ; else 0
    for (int idx = tid; idx < 4 * NBASIS; idx += 128) {
        const int i = idx / NBASIS;
        const int r = idx % NBASIS;
        const int md[4] = { r / 27, (r / 9) % 3, (r / 3) % 3, r % 3 };
        float sum = 0.0f;
        for (int k = 0; k < DIM; ++k) {
            for (int kp = 0; kp < DIM; ++kp) {
                int w = 1;
#pragma unroll
                for (int q = 0; q < NQ; ++q) {
                    const int kq  = (k  >> (3 - q)) & 1;
                    const int kqp = (kp >> (3 - q)) & 1;
                    const int mq  = md[q];
                    if (mq == 2) { if (kq == kqp) w = 0; }
                    else if (kq != kqp) w = 0;
                    else if (mq == 1 && kq) w = -w;
                }
                if (w > 0)      sum += sB[i * 256 + k * 16 + kp];
                else if (w < 0) sum -= sB[i * 256 + k * 16 + kp];
            }
        }
        const float t = sum * 0.0625f;   // 1/2^NQ
        g_T[(h * 4 + i) * NBASIS + r] = pk(t, t);
    }
}

// ============================================================================
// Kernel 2: ev for all tokens. 4 tokens/thread (two f32x2 pairs); factored
// 9x9 dot: ev_i = Σ_a m01[a] * (Σ_b T[a][b] * m23[b]).  T loads are
// warp-uniform (smem broadcast) and shared across both pairs.
// ============================================================================
__global__ __launch_bounds__(128) void ev_kernel(const float* __restrict__ x) {
    __shared__ ull sT[NH * 4 * NBASIS];   // 2592 * 8B = 20.25 KB
    for (int i = threadIdx.x; i < NH * 4 * NBASIS; i += 128) sT[i] = g_T[i];
    __syncthreads();

    const int gid = blockIdx.x * 128 + threadIdx.x;
    const int t0  = gid * 4;

#pragma unroll 1
    for (int h = 0; h < NH; ++h) {
        ull m01[2][9], m23[2][9];
#pragma unroll
        for (int p = 0; p < 2; ++p) {
            const int ta = t0 + 2 * p;
            float4 aa = *reinterpret_cast<const float4*>(x + (size_t)ta * EMB + h * 4);
            float4 ab = *reinterpret_cast<const float4*>(x + (size_t)(ta + 1) * EMB + h * 4);
            float c0a, s0a, c0b, s0b, c1a, s1a, c1b, s1b;
            float c2a, s2a, c2b, s2b, c3a, s3a, c3b, s3b;
            __sincosf(aa.x, &s0a, &c0a);  __sincosf(ab.x, &s0b, &c0b);
            __sincosf(aa.y, &s1a, &c1a);  __sincosf(ab.y, &s1b, &c1b);
            __sincosf(aa.z, &s2a, &c2a);  __sincosf(ab.z, &s2b, &c2b);
            __sincosf(aa.w, &s3a, &c3a);  __sincosf(ab.w, &s3b, &c3b);
            const ull C0 = pk(c0a, c0b), S0 = pk(s0a, s0b);
            const ull C1 = pk(c1a, c1b), S1 = pk(s1a, s1b);
            const ull C2 = pk(c2a, c2b), S2 = pk(s2a, s2b);
            const ull C3 = pk(c3a, c3b), S3 = pk(s3a, s3b);
            // basis a = m0*3+m1 over (1,C,S) of qubits 0,1 ; b likewise for 2,3
            m01[p][1] = C1;            m01[p][2] = S1;
            m01[p][3] = C0;            m01[p][6] = S0;
            m01[p][4] = f2mul(C0, C1); m01[p][5] = f2mul(C0, S1);
            m01[p][7] = f2mul(S0, C1); m01[p][8] = f2mul(S0, S1);
            m23[p][1] = C3;            m23[p][2] = S3;
            m23[p][3] = C2;            m23[p][6] = S2;
            m23[p][4] = f2mul(C2, C3); m23[p][5] = f2mul(C2, S3);
            m23[p][7] = f2mul(S2, C3); m23[p][8] = f2mul(S2, S3);
        }

        ull ev[2][4];
#pragma unroll
        for (int i = 0; i < 4; ++i) {
            const ull* T = sT + (h * 4 + i) * NBASIS;
#pragma unroll
            for (int a = 0; a < 9; ++a) {
                ull ta0 = T[a * 9];        // b = 0 term: m23 = 1
                ull ta1 = ta0;
#pragma unroll
                for (int b = 1; b < 9; ++b) {
                    const ull Tv = T[a * 9 + b];   // warp-uniform broadcast LDS
                    ta0 = f2fma(Tv, m23[0][b], ta0);
                    ta1 = f2fma(Tv, m23[1][b], ta1);
                }
                if (a == 0) { ev[0][i] = ta0; ev[1][i] = ta1; }   // m01[0] = 1
                else {
                    ev[0][i] = f2fma(ta0, m01[0][a], ev[0][i]);
                    ev[1][i] = f2fma(ta1, m01[1][a], ev[1][i]);
                }
            }
        }

#pragma unroll
        for (int p = 0; p < 2; ++p) {
            const int ta = t0 + 2 * p;
            float l0, h0, l1, h1, l2, h2, l3, h3;
            upk(ev[p][0], l0, h0); upk(ev[p][1], l1, h1);
            upk(ev[p][2], l2, h2); upk(ev[p][3], l3, h3);
            *reinterpret_cast<float4*>(g_ev + (size_t)ta * EMB + h * 4)       = make_float4(l0, l1, l2, l3);
            *reinterpret_cast<float4*>(g_ev + (size_t)(ta + 1) * EMB + h * 4) = make_float4(h0, h1, h2, h3);
        }
    }
}

// ============================================================================
// Kernel 3: out[t] = W * ev[t] + b.  2 tokens per thread (one f32x2 pair).
// ============================================================================
__global__ __launch_bounds__(128) void out_kernel(const float* __restrict__ W,
                                                  const float* __restrict__ bvec,
                                                  float* __restrict__ out) {
    __shared__ ulonglong2 sW[EMB * 16];   // [e][fpair] = {dup(W[e][2f]), dup(W[e][2f+1])}
    __shared__ float sb[EMB];
    for (int i = threadIdx.x; i < EMB * 16; i += blockDim.x) {
        int e = i >> 4, fp = i & 15;
        float w0 = W[e * 32 + fp * 2], w1 = W[e * 32 + fp * 2 + 1];
        ulonglong2 u; u.x = pk(w0, w0); u.y = pk(w1, w1);
        sW[i] = u;
    }
    if (threadIdx.x < EMB) sb[threadIdx.x] = bvec[threadIdx.x];
    __syncthreads();

    const int gid = blockIdx.x * blockDim.x + threadIdx.x;
    const int t0 = gid * 2, t1 = t0 + 1;

    ull ev2[32];
#pragma unroll
    for (int m = 0; m < 8; ++m) {
        float4 e0 = *reinterpret_cast<const float4*>(g_ev + (size_t)t0 * EMB + m * 4);
        float4 e1 = *reinterpret_cast<const float4*>(g_ev + (size_t)t1 * EMB + m * 4);
        ev2[m * 4 + 0] = pk(e0.x, e1.x);
        ev2[m * 4 + 1] = pk(e0.y, e1.y);
        ev2[m * 4 + 2] = pk(e0.z, e1.z);
        ev2[m * 4 + 3] = pk(e0.w, e1.w);
    }

#pragma unroll 1
    for (int eg = 0; eg < 8; ++eg) {
        float o0[4], o1[4];
#pragma unroll
        for (int r = 0; r < 4; ++r) {
            const int e = eg * 4 + r;
            float be = sb[e];
            ull acc = pk(be, be);
#pragma unroll
            for (int fp = 0; fp < 16; ++fp) {
                ulonglong2 w = sW[e * 16 + fp];
                acc = f2fma(w.x, ev2[fp * 2],     acc);
                acc = f2fma(w.y, ev2[fp * 2 + 1], acc);
            }
            upk(acc, o0[r], o1[r]);
        }
        *reinterpret_cast<float4*>(out + (size_t)t0 * EMB + eg * 4) = make_float4(o0[0], o0[1], o0[2], o0[3]);
        *reinterpret_cast<float4*>(out + (size_t)t1 * EMB + eg * 4) = make_float4(o1[0], o1[1], o1[2], o1[3]);
    }
}

// ============================================================================
extern "C" void kernel_launch(void* const* d_in, const int* in_sizes, int n_in,
                              void* d_out, int out_size) {
    // Identify inputs by element count (all distinct):
    // x: 32*4096*32 = 4194304, params: 8*2*4*3 = 192, W_out: 32*32 = 1024, b_out: 32
    const float* x = 0; const float* params = 0; const float* W = 0; const float* b = 0;
    for (int i = 0; i < n_in; ++i) {
        switch (in_sizes[i]) {
            case 4194304: x      = (const float*)d_in[i]; break;
            case 192:     params = (const float*)d_in[i]; break;
            case 1024:    W      = (const float*)d_in[i]; break;
            case 32:      b      = (const float*)d_in[i]; break;
            default: break;
        }
    }
    float* out = (float*)d_out;

    precompute_T_kernel<<<NH, 128>>>(params);
    ev_kernel<<<256, 128>>>(x);          // 32768 threads * 4 tokens = 131072
    out_kernel<<<512, 128>>>(W, b, out); // 65536 threads * 2 tokens = 131072
}

// round 9
// speedup vs baseline: 1.8066x; 1.8066x over previous
#include <cuda_runtime.h>

// ============================================================================
// MultiHeadAttentionQuantum — algebraic form.
// Per (token, head): circuit = fixed 16x16 unitary U_h applied to the real
// rank-1 vector v = ⊗_q (cos(x_q/2), sin(x_q/2)).
//   ev_i = v^T B_i v,  B_i = Σ_j s_ij Re(U_j^† U_j)   (real symmetric)
// cos² = (1+C)/2, sin² = (1−C)/2, cos·sin = S/2  (C=cos x, S=sin x) ⇒
// ev_i is multilinear in {1, C_q, S_q}: 81 basis terms. T is built with a
// SEPARABLE per-qubit transform (4 cheap sweeps, not the 256-term brute
// force that cost 61 us). ev does a factored (9 x 9) dot with LDS.128
// (pair-of-dup'd-f32x2) T rows so the LSU pipe stays under the FMA pipe.
// ============================================================================

#define NQ      4
#define DIM     16
#define NH      8
#define NLAYERS 2
#define EMB     32
#define NTOK    (32 * 4096)
#define NBASIS  81
#define NROWS   (NH * 4 * 9)          // 288 T-rows (h, i, a)
#define ROWW    5                      // ulonglong2 slots per row (9 vals + pad)

typedef unsigned long long ull;

// ---- packed f32x2 helpers (Blackwell sm_103a) ------------------------------
__device__ __forceinline__ ull pk(float lo, float hi) {
    ull r; asm("mov.b64 %0, {%1, %2};" : "=l"(r) : "f"(lo), "f"(hi)); return r;
}
__device__ __forceinline__ void upk(ull v, float& lo, float& hi) {
    asm("mov.b64 {%0, %1}, %2;" : "=f"(lo), "=f"(hi) : "l"(v));
}
__device__ __forceinline__ ull f2mul(ull a, ull b) {
    ull d; asm("mul.rn.f32x2 %0, %1, %2;" : "=l"(d) : "l"(a), "l"(b)); return d;
}
__device__ __forceinline__ ull f2fma(ull a, ull b, ull c) {
    ull d; asm("fma.rn.f32x2 %0, %1, %2, %3;" : "=l"(d) : "l"(a), "l"(b), "l"(c)); return d;
}

// ---- global scratch (static device arrays; no allocation) ------------------
__device__ ulonglong2 g_T2[NROWS * ROWW];      // padded, dup'd T rows
__device__ float      g_ev[(size_t)NTOK * EMB]; // 16 MB scratch

// ============================================================================
// Gate helpers with COMPILE-TIME masks (static register indexing).
// ============================================================================
template<int M>
__device__ __forceinline__ void rot3(float* cr, float* ci, const float* p) {
    float c, s;
    __sincosf(0.5f * p[0], &s, &c);          // RX
#pragma unroll
    for (int j = 0; j < DIM; ++j) if (!(j & M)) {
        const int j1 = j | M;
        float a0r = cr[j],  a0i = ci[j];
        float a1r = cr[j1], a1i = ci[j1];
        cr[j]  = c * a0r + s * a1i;   ci[j]  = c * a0i - s * a1r;
        cr[j1] = c * a1r + s * a0i;   ci[j1] = c * a1i - s * a0r;
    }
    __sincosf(0.5f * p[1], &s, &c);          // RY
#pragma unroll
    for (int j = 0; j < DIM; ++j) if (!(j & M)) {
        const int j1 = j | M;
        float a0r = cr[j],  a0i = ci[j];
        float a1r = cr[j1], a1i = ci[j1];
        cr[j]  = c * a0r - s * a1r;   ci[j]  = c * a0i - s * a1i;
        cr[j1] = s * a0r + c * a1r;   ci[j1] = s * a0i + c * a1i;
    }
    __sincosf(0.5f * p[2], &s, &c);          // RZ
#pragma unroll
    for (int j = 0; j < DIM; ++j) if (!(j & M)) {
        const int j1 = j | M;
        float a0r = cr[j],  a0i = ci[j];
        float a1r = cr[j1], a1i = ci[j1];
        cr[j]  = c * a0r + s * a0i;   ci[j]  = c * a0i - s * a0r;
        cr[j1] = c * a1r - s * a1i;   ci[j1] = c * a1i + s * a1r;
    }
}

template<int CM, int TM>
__device__ __forceinline__ void cnot_g(float* cr, float* ci) {
#pragma unroll
    for (int j = 0; j < DIM; ++j) if ((j & CM) && !(j & TM)) {
        const int j1 = j | TM;
        float tr = cr[j]; cr[j] = cr[j1]; cr[j1] = tr;
        float ti = ci[j]; ci[j] = ci[j1]; ci[j1] = ti;
    }
}

// ============================================================================
// Kernel 1: per head, build U -> B_i -> T via SEPARABLE qubit sweeps.
// One block per head (8 blocks x 128 threads).
// ============================================================================
__global__ void precompute_T_kernel(const float* __restrict__ params) {
    __shared__ float sUr[DIM * DIM], sUi[DIM * DIM];
    __shared__ float sA[4 * 256];    // ping
    __shared__ float sC[4 * 192];    // pong (max intermediate = 768)
    const int h   = blockIdx.x;
    const int tid = threadIdx.x;

    // ---- stage 1: threads 0..15 each evolve one COLUMN of U ----
    if (tid < DIM) {
        float cr[DIM], ci[DIM];
#pragma unroll
        for (int j = 0; j < DIM; ++j) { cr[j] = (j == tid) ? 1.0f : 0.0f; ci[j] = 0.0f; }
#pragma unroll
        for (int l = 0; l < NLAYERS; ++l) {
            const float* pb = params + (h * NLAYERS + l) * NQ * 3;
            rot3<8>(cr, ci, pb + 0);
            rot3<4>(cr, ci, pb + 3);
            rot3<2>(cr, ci, pb + 6);
            rot3<1>(cr, ci, pb + 9);
            cnot_g<8, 4>(cr, ci);
            cnot_g<4, 2>(cr, ci);
            cnot_g<2, 1>(cr, ci);
            cnot_g<1, 8>(cr, ci);
        }
#pragma unroll
        for (int j = 0; j < DIM; ++j) { sUr[j * DIM + tid] = cr[j]; sUi[j * DIM + tid] = ci[j]; }
    }
    __syncthreads();

    // ---- stage 2: B_i[k][kp] = Σ_j s_ij (Ur_jk Ur_jkp + Ui_jk Ui_jkp) ----
    for (int idx = tid; idx < 4 * 256; idx += 128) {
        const int i  = idx >> 8;
        const int k  = (idx >> 4) & 15;
        const int kp = idx & 15;
        float sum = 0.0f;
#pragma unroll
        for (int j = 0; j < DIM; ++j) {
            float t = sUr[j * DIM + k] * sUr[j * DIM + kp]
                    + sUi[j * DIM + k] * sUi[j * DIM + kp];
            sum += ((j >> (3 - i)) & 1) ? -t : t;
        }
        sA[idx] = sum;
    }
    __syncthreads();

    // ---- stage 3: 4 separable sweeps, qubit q acts on the MSB of the
    // remaining k/kp bits. Layout before sweep s:
    //   (((i*3^s + m) * 2^R + k) * 2^R + kp),  R = 4 - s.
    // Per-qubit map: out[0]=in(0,0)+in(1,1); out[1]=in(0,0)-in(1,1);
    //                out[2]=in(0,1)+in(1,0).
    {
        float* bufs[2] = { sA, sC };
#pragma unroll
        for (int s = 0; s < 4; ++s) {
            const float* in  = bufs[s & 1];
            float*       outb = bufs[(s + 1) & 1];
            const int pow3 = (s == 0) ? 1 : (s == 1) ? 3 : (s == 2) ? 9 : 27;
            const int R    = 4 - s;
            const int half = 1 << (R - 1);
            const int full = 1 << R;
            const int nOut = 4 * pow3 * 3 * half * half;
            for (int o = tid; o < nOut; o += 128) {
                int t = o;
                const int kp_r = t % half;  t /= half;
                const int k_r  = t % half;  t /= half;
                const int mq   = t % 3;     t /= 3;
                const int m    = t % pow3;  t /= pow3;
                const int i    = t;
                const int base = ((i * pow3 + m) * full) * full;
                const int i00 = base + (0 * half + k_r) * full + (0 * half + kp_r);
                const int i11 = base + (1 * half + k_r) * full + (1 * half + kp_r);
                const int i01 = base + (0 * half + k_r) * full + (1 * half + kp_r);
                const int i10 = base + (1 * half + k_r) * full + (0 * half + kp_r);
                float v;
                if (mq == 0)      v = in[i00] + in[i11];
                else if (mq == 1) v = in[i00] - in[i11];
                else              v = in[i01] + in[i10];
                outb[o] = v;
            }
            __syncthreads();
        }
    }
    // final data in sA (after 4 sweeps ping-pongs back to bufs[0]): 4*81 values
    // laid out as (i*81 + m), m = m0*27 + m1*9 + m2*3 + m3 = a*9 + b.

    // ---- stage 4: write padded dup'd ul2 rows: row = (h*4+i)*9+a, slot j
    // holds {dup(T[b=2j]), dup(T[b=2j+1 or 0 pad])}, T = sA * 1/16.
    for (int slot = tid; slot < 4 * 9 * ROWW; slot += 128) {
        const int j = slot % ROWW;
        const int a = (slot / ROWW) % 9;
        const int i = slot / (ROWW * 9);
        const int b0 = 2 * j, b1 = 2 * j + 1;
        const float t0 = sA[i * NBASIS + a * 9 + b0] * 0.0625f;
        const float t1 = (b1 < 9) ? sA[i * NBASIS + a * 9 + b1] * 0.0625f : 0.0f;
        ulonglong2 u; u.x = pk(t0, t0); u.y = pk(t1, t1);
        g_T2[((h * 4 + i) * 9 + a) * ROWW + j] = u;
    }
}

// ============================================================================
// Kernel 2: ev for all tokens. 4 tokens/thread (two f32x2 pairs); factored
// 9x9 dot with LDS.128 T rows.  512 blocks x 64 threads for wave balance.
// ============================================================================
__global__ __launch_bounds__(64) void ev_kernel(const float* __restrict__ x) {
    __shared__ ulonglong2 sT2[NROWS * ROWW];   // 1440 * 16B = 22.5 KB
    for (int i = threadIdx.x; i < NROWS * ROWW; i += 64) sT2[i] = g_T2[i];
    __syncthreads();

    const int gid = blockIdx.x * 64 + threadIdx.x;
    const int t0  = gid * 4;

#pragma unroll 1
    for (int h = 0; h < NH; ++h) {
        ull m01[2][9], m23[2][9];
#pragma unroll
        for (int p = 0; p < 2; ++p) {
            const int ta = t0 + 2 * p;
            float4 aa = *reinterpret_cast<const float4*>(x + (size_t)ta * EMB + h * 4);
            float4 ab = *reinterpret_cast<const float4*>(x + (size_t)(ta + 1) * EMB + h * 4);
            float c0a, s0a, c0b, s0b, c1a, s1a, c1b, s1b;
            float c2a, s2a, c2b, s2b, c3a, s3a, c3b, s3b;
            __sincosf(aa.x, &s0a, &c0a);  __sincosf(ab.x, &s0b, &c0b);
            __sincosf(aa.y, &s1a, &c1a);  __sincosf(ab.y, &s1b, &c1b);
            __sincosf(aa.z, &s2a, &c2a);  __sincosf(ab.z, &s2b, &c2b);
            __sincosf(aa.w, &s3a, &c3a);  __sincosf(ab.w, &s3b, &c3b);
            const ull C0 = pk(c0a, c0b), S0 = pk(s0a, s0b);
            const ull C1 = pk(c1a, c1b), S1 = pk(s1a, s1b);
            const ull C2 = pk(c2a, c2b), S2 = pk(s2a, s2b);
            const ull C3 = pk(c3a, c3b), S3 = pk(s3a, s3b);
            m01[p][1] = C1;            m01[p][2] = S1;
            m01[p][3] = C0;            m01[p][6] = S0;
            m01[p][4] = f2mul(C0, C1); m01[p][5] = f2mul(C0, S1);
            m01[p][7] = f2mul(S0, C1); m01[p][8] = f2mul(S0, S1);
            m23[p][1] = C3;            m23[p][2] = S3;
            m23[p][3] = C2;            m23[p][6] = S2;
            m23[p][4] = f2mul(C2, C3); m23[p][5] = f2mul(C2, S3);
            m23[p][7] = f2mul(S2, C3); m23[p][8] = f2mul(S2, S3);
        }

        ull ev[2][4];
#pragma unroll
        for (int i = 0; i < 4; ++i) {
            const ulonglong2* Ti = sT2 + ((h * 4 + i) * 9) * ROWW;
#pragma unroll
            for (int a = 0; a < 9; ++a) {
                const ulonglong2* Tr = Ti + a * ROWW;
                ulonglong2 w = Tr[0];                 // {dup T0, dup T1}
                ull ta0 = f2fma(w.y, m23[0][1], w.x); // T0 + T1*m23_1
                ull ta1 = f2fma(w.y, m23[1][1], w.x);
#pragma unroll
                for (int j = 1; j < 4; ++j) {
                    w = Tr[j];                        // {dup T(2j), dup T(2j+1)}
                    ta0 = f2fma(w.x, m23[0][2 * j],     ta0);
                    ta0 = f2fma(w.y, m23[0][2 * j + 1], ta0);
                    ta1 = f2fma(w.x, m23[1][2 * j],     ta1);
                    ta1 = f2fma(w.y, m23[1][2 * j + 1], ta1);
                }
                w = Tr[4];                            // {dup T8, 0}
                ta0 = f2fma(w.x, m23[0][8], ta0);
                ta1 = f2fma(w.x, m23[1][8], ta1);
                if (a == 0) { ev[0][i] = ta0; ev[1][i] = ta1; }   // m01[0] = 1
                else {
                    ev[0][i] = f2fma(ta0, m01[0][a], ev[0][i]);
                    ev[1][i] = f2fma(ta1, m01[1][a], ev[1][i]);
                }
            }
        }

#pragma unroll
        for (int p = 0; p < 2; ++p) {
            const int ta = t0 + 2 * p;
            float l0, h0, l1, h1, l2, h2, l3, h3;
            upk(ev[p][0], l0, h0); upk(ev[p][1], l1, h1);
            upk(ev[p][2], l2, h2); upk(ev[p][3], l3, h3);
            *reinterpret_cast<float4*>(g_ev + (size_t)ta * EMB + h * 4)       = make_float4(l0, l1, l2, l3);
            *reinterpret_cast<float4*>(g_ev + (size_t)(ta + 1) * EMB + h * 4) = make_float4(h0, h1, h2, h3);
        }
    }
}

// ============================================================================
// Kernel 3: out[t] = W * ev[t] + b.  2 tokens per thread (one f32x2 pair).
// ============================================================================
__global__ __launch_bounds__(128) void out_kernel(const float* __restrict__ W,
                                                  const float* __restrict__ bvec,
                                                  float* __restrict__ out) {
    __shared__ ulonglong2 sW[EMB * 16];
    __shared__ float sb[EMB];
    for (int i = threadIdx.x; i < EMB * 16; i += blockDim.x) {
        int e = i >> 4, fp = i & 15;
        float w0 = W[e * 32 + fp * 2], w1 = W[e * 32 + fp * 2 + 1];
        ulonglong2 u; u.x = pk(w0, w0); u.y = pk(w1, w1);
        sW[i] = u;
    }
    if (threadIdx.x < EMB) sb[threadIdx.x] = bvec[threadIdx.x];
    __syncthreads();

    const int gid = blockIdx.x * blockDim.x + threadIdx.x;
    const int t0 = gid * 2, t1 = t0 + 1;

    ull ev2[32];
#pragma unroll
    for (int m = 0; m < 8; ++m) {
        float4 e0 = *reinterpret_cast<const float4*>(g_ev + (size_t)t0 * EMB + m * 4);
        float4 e1 = *reinterpret_cast<const float4*>(g_ev + (size_t)t1 * EMB + m * 4);
        ev2[m * 4 + 0] = pk(e0.x, e1.x);
        ev2[m * 4 + 1] = pk(e0.y, e1.y);
        ev2[m * 4 + 2] = pk(e0.z, e1.z);
        ev2[m * 4 + 3] = pk(e0.w, e1.w);
    }

#pragma unroll 1
    for (int eg = 0; eg < 8; ++eg) {
        float o0[4], o1[4];
#pragma unroll
        for (int r = 0; r < 4; ++r) {
            const int e = eg * 4 + r;
            float be = sb[e];
            ull acc = pk(be, be);
#pragma unroll
            for (int fp = 0; fp < 16; ++fp) {
                ulonglong2 w = sW[e * 16 + fp];
                acc = f2fma(w.x, ev2[fp * 2],     acc);
                acc = f2fma(w.y, ev2[fp * 2 + 1], acc);
            }
            upk(acc, o0[r], o1[r]);
        }
        *reinterpret_cast<float4*>(out + (size_t)t0 * EMB + eg * 4) = make_float4(o0[0], o0[1], o0[2], o0[3]);
        *reinterpret_cast<float4*>(out + (size_t)t1 * EMB + eg * 4) = make_float4(o1[0], o1[1], o1[2], o1[3]);
    }
}

// ============================================================================
extern "C" void kernel_launch(void* const* d_in, const int* in_sizes, int n_in,
                              void* d_out, int out_size) {
    // Identify inputs by element count (all distinct):
    // x: 4194304, params: 192, W_out: 1024, b_out: 32
    const float* x = 0; const float* params = 0; const float* W = 0; const float* b = 0;
    for (int i = 0; i < n_in; ++i) {
        switch (in_sizes[i]) {
            case 4194304: x      = (const float*)d_in[i]; break;
            case 192:     params = (const float*)d_in[i]; break;
            case 1024:    W      = (const float*)d_in[i]; break;
            case 32:      b      = (const float*)d_in[i]; break;
            default: break;
        }
    }
    float* out = (float*)d_out;

    precompute_T_kernel<<<NH, 128>>>(params);
    ev_kernel<<<512, 64>>>(x);           // 32768 threads * 4 tokens = 131072
    out_kernel<<<512, 128>>>(W, b, out); // 65536 threads * 2 tokens = 131072
}